// round 2
// baseline (speedup 1.0000x reference)
#include <cuda_runtime.h>

#define BB 8
#define LL 512
#define DD 128

// Scratch (allocation-free rule: __device__ globals)
__device__ float g_qT[BB * DD * LL];  // [b][e][l]  (transposed projection u(inp))
__device__ float g_k [BB * LL * DD];  // [b][l][e]  (projection v(inp))

__device__ __forceinline__ float tanh_fast(float x) {
    float y;
    asm("tanh.approx.f32 %0, %1;" : "=f"(y) : "f"(x));
    return y;
}

// ---------------------------------------------------------------------------
// Kernel A: q = inp @ u_w^T (stored transposed), k = inp @ v_w^T (row-major)
// grid = B * (L/32) = 128 blocks, 256 threads.
// Per-thread micro-tile: 4 rows x 4 cols for BOTH matrices (32 accumulators).
// Weights staged in smem with pitch 33 -> conflict-free column reads.
// ---------------------------------------------------------------------------
__global__ __launch_bounds__(256, 2) void proj_kernel(
    const float* __restrict__ inp,
    const float* __restrict__ uw,
    const float* __restrict__ vw)
{
    __shared__ float xS[32][32];
    __shared__ float wuS[128][33];
    __shared__ float wvS[128][33];

    const int b    = blockIdx.x >> 4;          // 16 blocks per batch
    const int l0   = (blockIdx.x & 15) << 5;   // 32 rows per block
    const int t    = threadIdx.x;
    const int lane = t & 31;
    const int warp = t >> 5;
    const int lrow = warp << 2;                // 4 rows per warp

    float qacc[4][4], kacc[4][4];
#pragma unroll
    for (int i = 0; i < 4; i++)
#pragma unroll
        for (int jj = 0; jj < 4; jj++) { qacc[i][jj] = 0.f; kacc[i][jj] = 0.f; }

    for (int kc = 0; kc < 4; kc++) {
        const int d0 = kc << 5;
        for (int idx = t; idx < 32 * 32; idx += 256) {
            int r = idx >> 5, c = idx & 31;
            xS[r][c] = inp[(b * LL + l0 + r) * DD + d0 + c];
        }
        for (int idx = t; idx < 128 * 32; idx += 256) {
            int r = idx >> 5, c = idx & 31;
            wuS[r][c] = uw[r * DD + d0 + c];
            wvS[r][c] = vw[r * DD + d0 + c];
        }
        __syncthreads();

#pragma unroll 8
        for (int d = 0; d < 32; d++) {
            const float x0 = xS[lrow + 0][d];
            const float x1 = xS[lrow + 1][d];
            const float x2 = xS[lrow + 2][d];
            const float x3 = xS[lrow + 3][d];
#pragma unroll
            for (int jj = 0; jj < 4; jj++) {
                const int e = lane + (jj << 5);   // lanes -> consecutive e: no LDS conflict
                const float wu = wuS[e][d];
                const float wv = wvS[e][d];
                qacc[0][jj] = fmaf(x0, wu, qacc[0][jj]);
                qacc[1][jj] = fmaf(x1, wu, qacc[1][jj]);
                qacc[2][jj] = fmaf(x2, wu, qacc[2][jj]);
                qacc[3][jj] = fmaf(x3, wu, qacc[3][jj]);
                kacc[0][jj] = fmaf(x0, wv, kacc[0][jj]);
                kacc[1][jj] = fmaf(x1, wv, kacc[1][jj]);
                kacc[2][jj] = fmaf(x2, wv, kacc[2][jj]);
                kacc[3][jj] = fmaf(x3, wv, kacc[3][jj]);
            }
        }
        __syncthreads();
    }

#pragma unroll
    for (int i = 0; i < 4; i++) {
        const int l = l0 + lrow + i;
#pragma unroll
        for (int jj = 0; jj < 4; jj++) {
            const int e = lane + (jj << 5);
            g_qT[(b * DD + e) * LL + l] = qacc[i][jj];   // scattered (4MB total, cheap)
            g_k [(b * LL + l) * DD + e] = kacc[i][jj];   // coalesced
        }
    }
}

// ---------------------------------------------------------------------------
// Kernel B: fused score(tanh) + softmax + attn-write + out GEMM.
// grid = B * (L/8) = 512 blocks, 512 threads (16 warps).
// Warp w owns j in [32w, 32w+32); block owns 8 i-rows.
// Phase 2 is the MUFU.TANH-bound mainloop (the roofline).
// ---------------------------------------------------------------------------
__global__ __launch_bounds__(512, 2) void attn_kernel(
    const float* __restrict__ inp,
    const float* __restrict__ aw,
    float* __restrict__ out,
    float* __restrict__ attn)
{
    __shared__ __align__(16) float kS[8][128];
    __shared__ __align__(16) float aS[128];
    __shared__ float sc[8][512];
    __shared__ __align__(16) float outS[2][8][128];

    const int b    = blockIdx.x >> 6;          // 64 blocks per batch
    const int i0   = (blockIdx.x & 63) << 3;   // 8 i-rows per block
    const int t    = threadIdx.x;
    const int lane = t & 31;
    const int w    = t >> 5;

    // Stage k rows for this block's i-tile + the attention vector a
    for (int idx = t; idx < 8 * 128; idx += 512)
        kS[idx >> 7][idx & 127] = g_k[(b * LL + i0) * DD + idx];
    if (t < 128) aS[t] = aw[t];
    __syncthreads();

    // ---- Phase 2: score[i0+ii][j] = sum_d a_d * tanh(q[j][d] + k[i][d]) ----
    const int j = (w << 5) + lane;
    float acc[8];
#pragma unroll
    for (int ii = 0; ii < 8; ii++) acc[ii] = 0.f;

    const float* __restrict__ qcol = g_qT + b * DD * LL + j;
#pragma unroll 2
    for (int d4 = 0; d4 < 32; d4++) {
        const int d = d4 << 2;
        const float q0 = qcol[(d + 0) * LL];   // coalesced 128B per warp
        const float q1 = qcol[(d + 1) * LL];
        const float q2 = qcol[(d + 2) * LL];
        const float q3 = qcol[(d + 3) * LL];
        const float4 a4 = *(const float4*)&aS[d];
#pragma unroll
        for (int ii = 0; ii < 8; ii++) {
            const float4 kv = *(const float4*)&kS[ii][d];  // broadcast LDS.128
            float s;
            s = tanh_fast(q0 + kv.x); acc[ii] = fmaf(a4.x, s, acc[ii]);
            s = tanh_fast(q1 + kv.y); acc[ii] = fmaf(a4.y, s, acc[ii]);
            s = tanh_fast(q2 + kv.z); acc[ii] = fmaf(a4.z, s, acc[ii]);
            s = tanh_fast(q3 + kv.w); acc[ii] = fmaf(a4.w, s, acc[ii]);
        }
    }
#pragma unroll
    for (int ii = 0; ii < 8; ii++) sc[ii][j] = acc[ii];
    __syncthreads();

    // ---- Phase 3: softmax over j (axis 2), one warp per i-row ----
    if (w < 8) {
        const int r = w;
        float v[16];
        float mx = -1e30f;
#pragma unroll
        for (int q = 0; q < 16; q++) { v[q] = sc[r][lane + (q << 5)]; mx = fmaxf(mx, v[q]); }
#pragma unroll
        for (int o = 16; o > 0; o >>= 1) mx = fmaxf(mx, __shfl_xor_sync(0xffffffffu, mx, o));
        float s = 0.f;
#pragma unroll
        for (int q = 0; q < 16; q++) { v[q] = __expf(v[q] - mx); s += v[q]; }
#pragma unroll
        for (int o = 16; o > 0; o >>= 1) s += __shfl_xor_sync(0xffffffffu, s, o);
        const float inv = 1.0f / s;
        float* arow = attn + (b * LL + i0 + r) * LL;
#pragma unroll
        for (int q = 0; q < 16; q++) {
            const int jj = lane + (q << 5);
            const float av = v[q] * inv;
            sc[r][jj] = av;       // reuse for GEMM
            arow[jj]  = av;       // coalesced attn output
        }
    }
    __syncthreads();

    // ---- Phase 4: out[i,:] = sum_j attn[i,j] * inp[b,j,:]  (j split over 2 halves) ----
    {
        const int r = w & 7, h = w >> 3;
        float4 racc = make_float4(0.f, 0.f, 0.f, 0.f);
        const float4* __restrict__ xin =
            (const float4*)(inp + (size_t)(b * LL + (h << 8)) * DD) + lane;
#pragma unroll 8
        for (int jj = 0; jj < 256; jj++) {
            const float av = sc[r][(h << 8) + jj];    // broadcast
            const float4 xv = xin[jj * (DD / 4)];     // coalesced LDG.128
            racc.x = fmaf(av, xv.x, racc.x);
            racc.y = fmaf(av, xv.y, racc.y);
            racc.z = fmaf(av, xv.z, racc.z);
            racc.w = fmaf(av, xv.w, racc.w);
        }
        *(float4*)&outS[h][r][lane << 2] = racc;
    }
    __syncthreads();
    if (w < 8) {
        const int r = w;
        const float4 o0 = *(const float4*)&outS[0][r][lane << 2];
        const float4 o1 = *(const float4*)&outS[1][r][lane << 2];
        float4 o = make_float4(o0.x + o1.x, o0.y + o1.y, o0.z + o1.z, o0.w + o1.w);
        *(float4*)&out[(b * LL + i0 + r) * DD + (lane << 2)] = o;
    }
}

// ---------------------------------------------------------------------------
// Launch: inputs in metadata order inp, u_w, v_w, a_w.
// Output = tuple (out [B,L,D], attn [B,L,L]) concatenated -> 524288 + 2097152 floats.
// ---------------------------------------------------------------------------
extern "C" void kernel_launch(void* const* d_in, const int* in_sizes, int n_in,
                              void* d_out, int out_size)
{
    const float* inp = (const float*)d_in[0];
    const float* uw  = (const float*)d_in[1];
    const float* vw  = (const float*)d_in[2];
    const float* aw  = (const float*)d_in[3];

    float* out  = (float*)d_out;
    float* attn = out + BB * LL * DD;

    proj_kernel<<<BB * (LL / 32), 256>>>(inp, uw, vw);
    attn_kernel<<<BB * (LL / 8), 512>>>(inp, aw, out, attn);
}

// round 4
// speedup vs baseline: 1.0549x; 1.0549x over previous
#include <cuda_runtime.h>
#include <cuda_fp16.h>

#define BB 8
#define LL 512
#define DD 128

// Scratch (allocation-free rule: __device__ globals)
__device__ __half g_qh[BB * DD * LL];  // [b][d][l]  half, l contiguous (q projection)
__device__ float  g_k [BB * LL * DD];  // [b][l][e]  fp32 (k projection)

__device__ __forceinline__ __half2 tanh2_fast(__half2 x) {
    unsigned int xi = *(unsigned int*)&x, yi;
    asm("tanh.approx.f16x2 %0, %1;" : "=r"(yi) : "r"(xi));
    return *(__half2*)&yi;
}

// ---------------------------------------------------------------------------
// Kernel A: q = inp @ u_w^T (stored transposed as half [b][d][l]),
//           k = inp @ v_w^T (row-major fp32)
// grid = B * (L/32) = 128 blocks, 256 threads.
// ---------------------------------------------------------------------------
__global__ __launch_bounds__(256, 2) void proj_kernel(
    const float* __restrict__ inp,
    const float* __restrict__ uw,
    const float* __restrict__ vw)
{
    __shared__ float xS[32][32];
    __shared__ float wuS[128][33];
    __shared__ float wvS[128][33];

    const int b    = blockIdx.x >> 4;
    const int l0   = (blockIdx.x & 15) << 5;
    const int t    = threadIdx.x;
    const int lane = t & 31;
    const int warp = t >> 5;
    const int lrow = warp << 2;                // 4 consecutive l-rows per thread

    float qacc[4][4], kacc[4][4];
#pragma unroll
    for (int i = 0; i < 4; i++)
#pragma unroll
        for (int jj = 0; jj < 4; jj++) { qacc[i][jj] = 0.f; kacc[i][jj] = 0.f; }

    for (int kc = 0; kc < 4; kc++) {
        const int d0 = kc << 5;
        for (int idx = t; idx < 32 * 32; idx += 256) {
            int r = idx >> 5, c = idx & 31;
            xS[r][c] = inp[(b * LL + l0 + r) * DD + d0 + c];
        }
        for (int idx = t; idx < 128 * 32; idx += 256) {
            int r = idx >> 5, c = idx & 31;
            wuS[r][c] = uw[r * DD + d0 + c];
            wvS[r][c] = vw[r * DD + d0 + c];
        }
        __syncthreads();

#pragma unroll 8
        for (int d = 0; d < 32; d++) {
            const float x0 = xS[lrow + 0][d];
            const float x1 = xS[lrow + 1][d];
            const float x2 = xS[lrow + 2][d];
            const float x3 = xS[lrow + 3][d];
#pragma unroll
            for (int jj = 0; jj < 4; jj++) {
                const int e = lane + (jj << 5);
                const float wu = wuS[e][d];
                const float wv = wvS[e][d];
                qacc[0][jj] = fmaf(x0, wu, qacc[0][jj]);
                qacc[1][jj] = fmaf(x1, wu, qacc[1][jj]);
                qacc[2][jj] = fmaf(x2, wu, qacc[2][jj]);
                qacc[3][jj] = fmaf(x3, wu, qacc[3][jj]);
                kacc[0][jj] = fmaf(x0, wv, kacc[0][jj]);
                kacc[1][jj] = fmaf(x1, wv, kacc[1][jj]);
                kacc[2][jj] = fmaf(x2, wv, kacc[2][jj]);
                kacc[3][jj] = fmaf(x3, wv, kacc[3][jj]);
            }
        }
        __syncthreads();
    }

    __half2* qh2 = (__half2*)g_qh;
#pragma unroll
    for (int jj = 0; jj < 4; jj++) {
        const int e = lane + (jj << 5);
        // q: pack pairs over l (l0+lrow even), store half2 at [b][e][l]
#pragma unroll
        for (int i = 0; i < 4; i += 2) {
            __half2 hq = __halves2half2(__float2half(qacc[i][jj]),
                                        __float2half(qacc[i + 1][jj]));
            qh2[(((size_t)b * DD + e) * LL + l0 + lrow + i) >> 1] = hq;
        }
        // k: coalesced fp32
#pragma unroll
        for (int i = 0; i < 4; i++)
            g_k[((size_t)b * LL + l0 + lrow + i) * DD + e] = kacc[i][jj];
    }
}

// ---------------------------------------------------------------------------
// Kernel B: fused score(f16x2 tanh) + softmax + attn-write + out GEMM.
// grid = B * (L/8) = 512 blocks, 512 threads (16 warps).
// Warp w: d-half h = w>>3 (64 d's), j-tile jb = (w&7)*64 (64 j's, 2 per lane).
// Partial scores per d-half combined in smem before softmax.
// ---------------------------------------------------------------------------
__global__ __launch_bounds__(512, 2) void attn_kernel(
    const float* __restrict__ inp,
    const float* __restrict__ aw,
    float* __restrict__ out,
    float* __restrict__ attn)
{
    __shared__ __align__(16) __half2 kS2[8][128];   // k duplicated in both lanes
    __shared__ __align__(16) float aS[128];
    __shared__ float scp[2][8][512];                // per-d-half partial scores
    __shared__ __align__(16) float outS[2][8][128];

    const int b    = blockIdx.x >> 6;
    const int i0   = (blockIdx.x & 63) << 3;
    const int t    = threadIdx.x;
    const int lane = t & 31;
    const int w    = t >> 5;

    // Stage k (fp32 -> duplicated half2) and a
    for (int idx = t; idx < 8 * 128; idx += 512) {
        const int ii = idx >> 7, d = idx & 127;
        __half kh = __float2half(g_k[((size_t)b * LL + i0 + ii) * DD + d]);
        kS2[ii][d] = __halves2half2(kh, kh);
    }
    if (t < 128) aS[t] = aw[t];
    __syncthreads();

    // ---- Phase 2: partial score over this warp's 64 d's, 64 j's (2/lane) ----
    const int h     = w >> 3;
    const int jb    = (w & 7) << 6;
    const int dbase = h << 6;

    float acc0[8], acc1[8];
#pragma unroll
    for (int ii = 0; ii < 8; ii++) { acc0[ii] = 0.f; acc1[ii] = 0.f; }

    const __half2* __restrict__ qp =
        (const __half2*)g_qh + (size_t)b * DD * (LL >> 1) + (jb >> 1) + lane;

#pragma unroll 2
    for (int d2 = 0; d2 < 32; d2++) {
        const int d = dbase + (d2 << 1);
        const __half2 qa = qp[(size_t)d * (LL >> 1)];        // coalesced 128B
        const __half2 qb = qp[(size_t)(d + 1) * (LL >> 1)];
        const float2 a01 = *(const float2*)&aS[d];
#pragma unroll
        for (int ii = 0; ii < 8; ii++) {
            const __half2 ka = kS2[ii][d];       // LDS.64 broadcast (adjacent)
            const __half2 kb = kS2[ii][d + 1];
            const __half2 ta = tanh2_fast(__hadd2(qa, ka));   // two independent
            const __half2 tb = tanh2_fast(__hadd2(qb, kb));   // MUFU chains
            const float2 fa = __half22float2(ta);
            const float2 fb = __half22float2(tb);
            acc0[ii] = fmaf(a01.x, fa.x, acc0[ii]);
            acc1[ii] = fmaf(a01.x, fa.y, acc1[ii]);
            acc0[ii] = fmaf(a01.y, fb.x, acc0[ii]);
            acc1[ii] = fmaf(a01.y, fb.y, acc1[ii]);
        }
    }
    {
        const int j = jb + (lane << 1);
#pragma unroll
        for (int ii = 0; ii < 8; ii++) {
            scp[h][ii][j]     = acc0[ii];
            scp[h][ii][j + 1] = acc1[ii];
        }
    }
    __syncthreads();

    // ---- Phase 3: softmax over j, one warp per i-row ----
    if (w < 8) {
        const int r = w;
        float v[16];
        float mx = -1e30f;
#pragma unroll
        for (int q = 0; q < 16; q++) {
            const int jj = lane + (q << 5);
            v[q] = scp[0][r][jj] + scp[1][r][jj];
            mx = fmaxf(mx, v[q]);
        }
#pragma unroll
        for (int o = 16; o > 0; o >>= 1) mx = fmaxf(mx, __shfl_xor_sync(0xffffffffu, mx, o));
        float s = 0.f;
#pragma unroll
        for (int q = 0; q < 16; q++) { v[q] = __expf(v[q] - mx); s += v[q]; }
#pragma unroll
        for (int o = 16; o > 0; o >>= 1) s += __shfl_xor_sync(0xffffffffu, s, o);
        const float inv = 1.0f / s;
        float* arow = attn + ((size_t)b * LL + i0 + r) * LL;
#pragma unroll
        for (int q = 0; q < 16; q++) {
            const int jj = lane + (q << 5);
            const float av = v[q] * inv;
            scp[0][r][jj] = av;   // reuse for GEMM
            arow[jj]      = av;   // coalesced attn output
        }
    }
    __syncthreads();

    // ---- Phase 4: out[i,:] = sum_j attn[i,j] * inp[b,j,:] (j split in halves) ----
    {
        const int r = w & 7, hh = w >> 3;
        float4 racc = make_float4(0.f, 0.f, 0.f, 0.f);
        const float4* __restrict__ xin =
            (const float4*)(inp + (size_t)(b * LL + (hh << 8)) * DD) + lane;
#pragma unroll 8
        for (int jj = 0; jj < 256; jj++) {
            const float av = scp[0][r][(hh << 8) + jj];   // broadcast
            const float4 xv = xin[jj * (DD / 4)];         // coalesced LDG.128
            racc.x = fmaf(av, xv.x, racc.x);
            racc.y = fmaf(av, xv.y, racc.y);
            racc.z = fmaf(av, xv.z, racc.z);
            racc.w = fmaf(av, xv.w, racc.w);
        }
        *(float4*)&outS[hh][r][lane << 2] = racc;
    }
    __syncthreads();
    if (w < 8) {
        const int r = w;
        const float4 o0 = *(const float4*)&outS[0][r][lane << 2];
        const float4 o1 = *(const float4*)&outS[1][r][lane << 2];
        float4 o = make_float4(o0.x + o1.x, o0.y + o1.y, o0.z + o1.z, o0.w + o1.w);
        *(float4*)&out[((size_t)b * LL + i0 + r) * DD + (lane << 2)] = o;
    }
}

// ---------------------------------------------------------------------------
// Launch: inputs in metadata order inp, u_w, v_w, a_w.
// Output = (out [B,L,D], attn [B,L,L]) concatenated.
// ---------------------------------------------------------------------------
extern "C" void kernel_launch(void* const* d_in, const int* in_sizes, int n_in,
                              void* d_out, int out_size)
{
    const float* inp = (const float*)d_in[0];
    const float* uw  = (const float*)d_in[1];
    const float* vw  = (const float*)d_in[2];
    const float* aw  = (const float*)d_in[3];

    float* out  = (float*)d_out;
    float* attn = out + BB * LL * DD;

    proj_kernel<<<BB * (LL / 32), 256>>>(inp, uw, vw);
    attn_kernel<<<BB * (LL / 8), 512>>>(inp, aw, out, attn);
}